// round 8
// baseline (speedup 1.0000x reference)
#include <cuda_runtime.h>
#include <cuda_bf16.h>
#include <stdint.h>

#define NB 8
#define NS 1024
#define ND 1024
#define NH 16
#define NHD 64

// Static device scratch. bf16 hi/lo split operands. g_wh/g_wl natural [k][n].
static __device__ __align__(16) __nv_bfloat16 g_xh[(size_t)NB * NS * ND];
static __device__ __align__(16) __nv_bfloat16 g_xl[(size_t)NB * NS * ND];
static __device__ __align__(16) __nv_bfloat16 g_wh[3][(size_t)ND * ND];
static __device__ __align__(16) __nv_bfloat16 g_wl[3][(size_t)ND * ND];
static __device__ __align__(16) __nv_bfloat16 g_qh[(size_t)NB * NH * NS * NHD];
static __device__ __align__(16) __nv_bfloat16 g_ql[(size_t)NB * NH * NS * NHD];
static __device__ __align__(16) __nv_bfloat16 g_kh[(size_t)NB * NH * NS * NHD];
static __device__ __align__(16) __nv_bfloat16 g_kl[(size_t)NB * NH * NS * NHD];
static __device__ __align__(16) __nv_bfloat16 g_vh[(size_t)NB * NH * NS * NHD];
static __device__ __align__(16) __nv_bfloat16 g_vl[(size_t)NB * NH * NS * NHD];
static __device__ __align__(16) uint8_t       g_m8[(size_t)NB * NS * NS];

// ---------------------------------------------------------------------------
__device__ __forceinline__ uint32_t smem_u32(const void* p) {
    uint32_t a;
    asm("{ .reg .u64 t; cvta.to.shared.u64 t, %1; cvt.u32.u64 %0, t; }"
        : "=r"(a) : "l"(p));
    return a;
}
__device__ __forceinline__ void ldsm4(uint32_t* r, uint32_t a) {
    asm volatile("ldmatrix.sync.aligned.m8n8.x4.shared.b16 {%0,%1,%2,%3}, [%4];"
                 : "=r"(r[0]), "=r"(r[1]), "=r"(r[2]), "=r"(r[3]) : "r"(a));
}
__device__ __forceinline__ void ldsm4t(uint32_t* r, uint32_t a) {
    asm volatile("ldmatrix.sync.aligned.m8n8.x4.trans.shared.b16 {%0,%1,%2,%3}, [%4];"
                 : "=r"(r[0]), "=r"(r[1]), "=r"(r[2]), "=r"(r[3]) : "r"(a));
}
__device__ __forceinline__ void mma16816(float* c, const uint32_t* a,
                                         uint32_t b0, uint32_t b1) {
    asm volatile(
        "mma.sync.aligned.m16n8k16.row.col.f32.bf16.bf16.f32 "
        "{%0,%1,%2,%3},{%4,%5,%6,%7},{%8,%9},{%0,%1,%2,%3};"
        : "+f"(c[0]), "+f"(c[1]), "+f"(c[2]), "+f"(c[3])
        : "r"(a[0]), "r"(a[1]), "r"(a[2]), "r"(a[3]), "r"(b0), "r"(b1));
}
#define CPA16(s, g) \
    asm volatile("cp.async.cg.shared.global [%0], [%1], 16;" :: "r"(s), "l"(g))
#define CPC()  asm volatile("cp.async.commit_group;" ::: "memory")
#define CPW0() asm volatile("cp.async.wait_group 0;" ::: "memory")
#define CPW1() asm volatile("cp.async.wait_group 1;" ::: "memory")

__device__ __forceinline__ uint32_t pkb(__nv_bfloat16 a, __nv_bfloat16 b) {
    return (uint32_t)__bfloat16_as_ushort(a) | ((uint32_t)__bfloat16_as_ushort(b) << 16);
}
__device__ __forceinline__ __nv_bfloat16 bfh(float v) { return __float2bfloat16_rn(v); }
__device__ __forceinline__ __nv_bfloat16 bfl(float v, __nv_bfloat16 h) {
    return __float2bfloat16_rn(v - __bfloat162float(h));
}

// ---------------------------------------------------------------------------
// prep: mask->u8, x->hi/lo, W->hi/lo (natural [k][n] layout)
// ---------------------------------------------------------------------------
__global__ void prep_mask(const float* __restrict__ m) {
    size_t i = (size_t)blockIdx.x * 256 + threadIdx.x;
    float4 v = ((const float4*)m)[i];
    ((uchar4*)g_m8)[i] = make_uchar4(v.x != 0.f, v.y != 0.f, v.z != 0.f, v.w != 0.f);
}
__device__ __forceinline__ void split_store(const float* src, __nv_bfloat16* dh,
                                            __nv_bfloat16* dl, size_t i) {
    float4 v = ((const float4*)src)[i];
    __nv_bfloat16 h0 = bfh(v.x), h1 = bfh(v.y), h2 = bfh(v.z), h3 = bfh(v.w);
    ((uint32_t*)dh)[2 * i]     = pkb(h0, h1);
    ((uint32_t*)dh)[2 * i + 1] = pkb(h2, h3);
    ((uint32_t*)dl)[2 * i]     = pkb(bfl(v.x, h0), bfl(v.y, h1));
    ((uint32_t*)dl)[2 * i + 1] = pkb(bfl(v.z, h2), bfl(v.w, h3));
}
__global__ void prep_x(const float* __restrict__ x) {
    split_store(x, g_xh, g_xl, (size_t)blockIdx.x * 256 + threadIdx.x);
}
__global__ void prep_w(const float* __restrict__ Wq, const float* __restrict__ Wk,
                       const float* __restrict__ Wv) {
    const float* W = blockIdx.y == 0 ? Wq : (blockIdx.y == 1 ? Wk : Wv);
    split_store(W, g_wh[blockIdx.y], g_wl[blockIdx.y],
                (size_t)blockIdx.x * 256 + threadIdx.x);
}

// ---------------------------------------------------------------------------
// QKV GEMM: C = X @ W (3x bf16-split HMMA). Block 128x128, 16 warps (2x8),
// warp tile 64x16, K-chunk 16, 3-stage cp.async pipeline (dynamic smem).
// Split-MMA variants issued in separate sweeps -> dependency distance 8.
// Epilogue splits to [b,h,s,hd]; Q *= 1/8.
// ---------------------------------------------------------------------------
// Per-stage byte offsets inside dynamic smem:
//   Ah: 0      (128 x 24 bf16 = 6144 B)
//   Al: 6144
//   Bh: 12288  (16 x 136 bf16 = 4352 B)
//   Bl: 16640
//   stage stride 20992 B, 3 stages -> 62976 B
#define GST 20992
__global__ __launch_bounds__(512, 1)
void qkv_gemm_hmma() {
    extern __shared__ __align__(16) char dsm[];

    const int tid = threadIdx.x, lane = tid & 31, wid = tid >> 5;
    const int wm = wid >> 3, wn = wid & 7;           // 2 x 8 warp grid
    const int z = blockIdx.z;
    const int m0 = blockIdx.y * 128, n0 = blockIdx.x * 128;
    const __nv_bfloat16* wh = g_wh[z];
    const __nv_bfloat16* wl = g_wl[z];

    // copy mapping: threads 0-255 copy hi (A+B), 256-511 copy lo.
    const int t2 = tid & 255;
    const int ar = t2 >> 1, ac = (t2 & 1) * 8;       // A: 128r x 16c
    const int br = t2 >> 4, bc = (t2 & 15) * 8;      // B: 16r x 128c
    const bool lo_half = (tid >= 256);
    const __nv_bfloat16* srcA = lo_half ? g_xl : g_xh;
    const __nv_bfloat16* srcB = lo_half ? wl : wh;
    const uint32_t dstA_off = (lo_half ? 6144u : 0u) + (uint32_t)(ar * 24 + ac) * 2;
    const uint32_t dstB_off = (lo_half ? 16640u : 12288u) + (uint32_t)(br * 136 + bc) * 2;
    const uint32_t sbase = smem_u32(dsm);

    auto preload = [&](int c, int st) {
        const int k0 = c * 16;
        const uint32_t s0 = sbase + st * GST;
        CPA16(s0 + dstA_off, srcA + (size_t)(m0 + ar) * ND + k0 + ac);
        CPA16(s0 + dstB_off, srcB + (size_t)(k0 + br) * ND + n0 + bc);
    };

    float acc[4][2][4] = {};

    preload(0, 0); CPC();
    preload(1, 1); CPC();

    for (int c = 0; c < 64; ++c) {
        const int st = c - (c / 3) * 3;              // c % 3
        CPW1();                                      // group c done, c+1 may fly
        __syncthreads();
        if (c + 2 < 64) {
            int st2 = (c + 2) - ((c + 2) / 3) * 3;
            preload(c + 2, st2);
            CPC();
        }

        const uint32_t sb = sbase + st * GST;
        uint32_t ahf[4][4], alf[4][4], bhf[4], blf[4];
#pragma unroll
        for (int mt = 0; mt < 4; ++mt) {
            const uint32_t off =
                (uint32_t)((wm * 64 + mt * 16 + (lane & 15)) * 24 +
                           8 * ((lane >> 4) & 1)) * 2;
            ldsm4(ahf[mt], sb + off);
            ldsm4(alf[mt], sb + 6144 + off);
        }
        {
            const uint32_t boff =
                (uint32_t)((lane & 15) * 136 + wn * 16 + 8 * ((lane >> 4) & 1)) * 2;
            ldsm4t(bhf, sb + 12288 + boff);
            ldsm4t(blf, sb + 16640 + boff);
        }
        // hh sweep
#pragma unroll
        for (int mt = 0; mt < 4; ++mt)
#pragma unroll
            for (int nt = 0; nt < 2; ++nt)
                mma16816(acc[mt][nt], ahf[mt], bhf[2 * nt], bhf[2 * nt + 1]);
        // hl sweep
#pragma unroll
        for (int mt = 0; mt < 4; ++mt)
#pragma unroll
            for (int nt = 0; nt < 2; ++nt)
                mma16816(acc[mt][nt], ahf[mt], blf[2 * nt], blf[2 * nt + 1]);
        // lh sweep
#pragma unroll
        for (int mt = 0; mt < 4; ++mt)
#pragma unroll
            for (int nt = 0; nt < 2; ++nt)
                mma16816(acc[mt][nt], alf[mt], bhf[2 * nt], bhf[2 * nt + 1]);
    }

    // Epilogue: split + scatter to [b,h,s,hd]
    __nv_bfloat16 *dh, *dl;
    if (z == 0)      { dh = g_qh; dl = g_ql; }
    else if (z == 1) { dh = g_kh; dl = g_kl; }
    else             { dh = g_vh; dl = g_vl; }
    const float scale = (z == 0) ? 0.125f : 1.0f;
    const int g = lane >> 2, lam = lane & 3;
#pragma unroll
    for (int mt = 0; mt < 4; ++mt)
#pragma unroll
        for (int nt = 0; nt < 2; ++nt) {
            const int n = n0 + wn * 16 + nt * 8 + lam * 2;
            const int h = n >> 6, hd = n & (NHD - 1);
#pragma unroll
            for (int rr = 0; rr < 2; ++rr) {
                const int m = m0 + wm * 64 + mt * 16 + g + rr * 8;
                const int b = m >> 10, s = m & (NS - 1);
                const float c0 = acc[mt][nt][rr * 2 + 0] * scale;
                const float c1 = acc[mt][nt][rr * 2 + 1] * scale;
                __nv_bfloat16 h0 = bfh(c0), h1 = bfh(c1);
                const size_t idx = (((size_t)b * NH + h) * NS + s) * NHD + hd;
                *(uint32_t*)(dh + idx) = pkb(h0, h1);
                *(uint32_t*)(dl + idx) = pkb(bfl(c0, h0), bfl(c1, h1));
            }
        }
}

// ---------------------------------------------------------------------------
// Fused attention (HMMA). Block = 64 q-rows x (h,b); 4 warps x 16 q-rows.
// Q frags direct from global; K/V stream in 32-key cp.async double buffer.
// Split-MMA pairs interleaved across the two accumulators.
// ---------------------------------------------------------------------------
__global__ __launch_bounds__(128, 3)
void attn_tc(float* __restrict__ out) {
    __shared__ __nv_bfloat16 Ksh[2][32 * 72], Ksl[2][32 * 72];
    __shared__ __nv_bfloat16 Vsh[2][32 * 72], Vsl[2][32 * 72];

    const int tid = threadIdx.x, lane = tid & 31, wid = tid >> 5;
    const int qt = blockIdx.x, h = blockIdx.y, b = blockIdx.z;
    const size_t bh = (size_t)b * NH + h;
    const int g = lane >> 2, lam = lane & 3;

    const __nv_bfloat16* kh_g = g_kh + bh * NS * NHD;
    const __nv_bfloat16* kl_g = g_kl + bh * NS * NHD;
    const __nv_bfloat16* vh_g = g_vh + bh * NS * NHD;
    const __nv_bfloat16* vl_g = g_vl + bh * NS * NHD;

    uint32_t qfh[4][4], qfl[4][4];
    {
        const __nv_bfloat16* qh_g = g_qh + (bh * NS + (size_t)qt * 64) * NHD;
        const __nv_bfloat16* ql_g = g_ql + (bh * NS + (size_t)qt * 64) * NHD;
        const int r0 = wid * 16 + g, r1 = r0 + 8;
#pragma unroll
        for (int dt = 0; dt < 4; ++dt) {
            const int c = dt * 16 + lam * 2;
            qfh[dt][0] = *(const uint32_t*)(qh_g + (size_t)r0 * NHD + c);
            qfh[dt][1] = *(const uint32_t*)(qh_g + (size_t)r1 * NHD + c);
            qfh[dt][2] = *(const uint32_t*)(qh_g + (size_t)r0 * NHD + c + 8);
            qfh[dt][3] = *(const uint32_t*)(qh_g + (size_t)r1 * NHD + c + 8);
            qfl[dt][0] = *(const uint32_t*)(ql_g + (size_t)r0 * NHD + c);
            qfl[dt][1] = *(const uint32_t*)(ql_g + (size_t)r1 * NHD + c);
            qfl[dt][2] = *(const uint32_t*)(ql_g + (size_t)r0 * NHD + c + 8);
            qfl[dt][3] = *(const uint32_t*)(ql_g + (size_t)r1 * NHD + c + 8);
        }
    }

    auto preload = [&](int kt, int st) {
#pragma unroll
        for (int i = 0; i < 2; ++i) {
            const int idx = tid * 2 + i;
            const int r = idx >> 3, c8 = (idx & 7) * 8;
            const size_t gi = (size_t)(kt * 32 + r) * NHD + c8;
            const uint32_t so = smem_u32(&Ksh[st][r * 72 + c8]);
            const uint32_t d  = (uint32_t)((char*)Ksl - (char*)Ksh);
            const uint32_t dv = (uint32_t)((char*)Vsh - (char*)Ksh);
            const uint32_t dl2 = (uint32_t)((char*)Vsl - (char*)Ksh);
            CPA16(so,       kh_g + gi);
            CPA16(so + d,   kl_g + gi);
            CPA16(so + dv,  vh_g + gi);
            CPA16(so + dl2, vl_g + gi);
        }
    };

    float ctx[8][4] = {};
    float rs0 = 0.f, rs1 = 0.f;
    const int q0 = qt * 64 + wid * 16 + g;
    const uint8_t* mrow0 = g_m8 + ((size_t)b * NS + q0) * NS;
    const uint8_t* mrow1 = mrow0 + 8 * NS;

    preload(0, 0);
    CPC();

    for (int kts = 0; kts < 32; ++kts) {
        const int st = kts & 1;
        CPW0();
        __syncthreads();
        if (kts + 1 < 32) { preload(kts + 1, st ^ 1); CPC(); }

        float sacc[4][4] = {};
#pragma unroll
        for (int ntp = 0; ntp < 2; ++ntp) {
#pragma unroll
            for (int dt = 0; dt < 4; ++dt) {
                const uint32_t boff = smem_u32(
                    &Ksh[st][(ntp * 16 + 8 * ((lane >> 4) & 1) + (lane & 7)) * 72 +
                             dt * 16 + 8 * ((lane >> 3) & 1)]);
                uint32_t kb_h[4], kb_l[4];
                ldsm4(kb_h, boff);
                ldsm4(kb_l, boff + (uint32_t)((char*)Ksl - (char*)Ksh));
                float* s0 = sacc[2 * ntp];
                float* s1 = sacc[2 * ntp + 1];
                mma16816(s0, qfh[dt], kb_h[0], kb_h[1]);
                mma16816(s1, qfh[dt], kb_h[2], kb_h[3]);
                mma16816(s0, qfh[dt], kb_l[0], kb_l[1]);
                mma16816(s1, qfh[dt], kb_l[2], kb_l[3]);
                mma16816(s0, qfl[dt], kb_h[0], kb_h[1]);
                mma16816(s1, qfl[dt], kb_h[2], kb_h[3]);
            }
        }

        uint32_t pah[2][4], pal[2][4];
#pragma unroll
        for (int nt = 0; nt < 4; ++nt) {
            const int t = kts * 32 + nt * 8 + lam * 2;
            const uchar2 mc0 = *(const uchar2*)(mrow0 + t);
            const uchar2 mc1 = *(const uchar2*)(mrow1 + t);
            const float p0 = __expf(sacc[nt][0]) * (float)mc0.x;
            const float p1 = __expf(sacc[nt][1]) * (float)mc0.y;
            const float p2 = __expf(sacc[nt][2]) * (float)mc1.x;
            const float p3 = __expf(sacc[nt][3]) * (float)mc1.y;
            rs0 += p0 + p1;
            rs1 += p2 + p3;
            __nv_bfloat16 h0 = bfh(p0), h1 = bfh(p1), h2 = bfh(p2), h3 = bfh(p3);
            const int j = nt >> 1, o = (nt & 1) * 2;
            pah[j][o + 0] = pkb(h0, h1);
            pah[j][o + 1] = pkb(h2, h3);
            pal[j][o + 0] = pkb(bfl(p0, h0), bfl(p1, h1));
            pal[j][o + 1] = pkb(bfl(p2, h2), bfl(p3, h3));
        }

#pragma unroll
        for (int ntp = 0; ntp < 4; ++ntp) {
#pragma unroll
            for (int j = 0; j < 2; ++j) {
                const uint32_t voff = smem_u32(
                    &Vsh[st][(j * 16 + (lane & 15)) * 72 + ntp * 16 +
                             8 * ((lane >> 4) & 1)]);
                uint32_t vb_h[4], vb_l[4];
                ldsm4t(vb_h, voff);
                ldsm4t(vb_l, voff + (uint32_t)((char*)Vsl - (char*)Vsh));
                float* c0 = ctx[2 * ntp];
                float* c1 = ctx[2 * ntp + 1];
                mma16816(c0, pah[j], vb_h[0], vb_h[1]);
                mma16816(c1, pah[j], vb_h[2], vb_h[3]);
                mma16816(c0, pah[j], vb_l[0], vb_l[1]);
                mma16816(c1, pah[j], vb_l[2], vb_l[3]);
                mma16816(c0, pal[j], vb_h[0], vb_h[1]);
                mma16816(c1, pal[j], vb_h[2], vb_h[3]);
            }
        }
    }

    rs0 += __shfl_xor_sync(0xffffffffu, rs0, 1);
    rs0 += __shfl_xor_sync(0xffffffffu, rs0, 2);
    rs1 += __shfl_xor_sync(0xffffffffu, rs1, 1);
    rs1 += __shfl_xor_sync(0xffffffffu, rs1, 2);
    const float inv0 = 1.0f / (rs0 + 1e-8f);
    const float inv1 = 1.0f / (rs1 + 1e-8f);

#pragma unroll
    for (int nt = 0; nt < 8; ++nt) {
        const int d = nt * 8 + lam * 2;
        float* o0 = out + ((size_t)b * NS + q0) * ND + h * NHD + d;
        *(float2*)o0 = make_float2(ctx[nt][0] * inv0, ctx[nt][1] * inv0);
        *(float2*)(o0 + (size_t)8 * ND) =
            make_float2(ctx[nt][2] * inv1, ctx[nt][3] * inv1);
    }
}

// ---------------------------------------------------------------------------
extern "C" void kernel_launch(void* const* d_in, const int* in_sizes, int n_in,
                              void* d_out, int out_size) {
    (void)in_sizes; (void)n_in; (void)out_size;
    const float* x    = (const float*)d_in[0];
    const float* mask = (const float*)d_in[1];
    const float* Wq   = (const float*)d_in[2];
    const float* Wk   = (const float*)d_in[3];
    const float* Wv   = (const float*)d_in[4];
    float* out = (float*)d_out;

    static int attr_done = 0;
    if (!attr_done) {
        cudaFuncSetAttribute(qkv_gemm_hmma,
                             cudaFuncAttributeMaxDynamicSharedMemorySize, 3 * GST);
        attr_done = 1;
    }

    prep_mask<<<(NB * NS * NS) / 1024, 256>>>(mask);
    prep_x<<<(NB * NS * ND) / 1024, 256>>>(x);
    prep_w<<<dim3((ND * ND) / 1024, 3), 256>>>(Wq, Wk, Wv);
    qkv_gemm_hmma<<<dim3(ND / 128, (NB * NS) / 128, 3), 512, 3 * GST>>>();
    attn_tc<<<dim3(NS / 64, NH, NB), 128>>>(out);
}

// round 9
// speedup vs baseline: 1.1605x; 1.1605x over previous
#include <cuda_runtime.h>
#include <cuda_bf16.h>
#include <stdint.h>

#define NB 8
#define NS 1024
#define ND 1024
#define NH 16
#define NHD 64

// Static device scratch. bf16 hi/lo split operands. g_wh/g_wl natural [k][n].
static __device__ __align__(16) __nv_bfloat16 g_xh[(size_t)NB * NS * ND];
static __device__ __align__(16) __nv_bfloat16 g_xl[(size_t)NB * NS * ND];
static __device__ __align__(16) __nv_bfloat16 g_wh[3][(size_t)ND * ND];
static __device__ __align__(16) __nv_bfloat16 g_wl[3][(size_t)ND * ND];
static __device__ __align__(16) __nv_bfloat16 g_qh[(size_t)NB * NH * NS * NHD];
static __device__ __align__(16) __nv_bfloat16 g_ql[(size_t)NB * NH * NS * NHD];
static __device__ __align__(16) __nv_bfloat16 g_kh[(size_t)NB * NH * NS * NHD];
static __device__ __align__(16) __nv_bfloat16 g_kl[(size_t)NB * NH * NS * NHD];
static __device__ __align__(16) __nv_bfloat16 g_vh[(size_t)NB * NH * NS * NHD];
static __device__ __align__(16) __nv_bfloat16 g_vl[(size_t)NB * NH * NS * NHD];
static __device__ __align__(16) uint8_t       g_m8[(size_t)NB * NS * NS];

// ---------------------------------------------------------------------------
__device__ __forceinline__ uint32_t smem_u32(const void* p) {
    uint32_t a;
    asm("{ .reg .u64 t; cvta.to.shared.u64 t, %1; cvt.u32.u64 %0, t; }"
        : "=r"(a) : "l"(p));
    return a;
}
__device__ __forceinline__ void ldsm4(uint32_t* r, uint32_t a) {
    asm volatile("ldmatrix.sync.aligned.m8n8.x4.shared.b16 {%0,%1,%2,%3}, [%4];"
                 : "=r"(r[0]), "=r"(r[1]), "=r"(r[2]), "=r"(r[3]) : "r"(a));
}
__device__ __forceinline__ void ldsm4t(uint32_t* r, uint32_t a) {
    asm volatile("ldmatrix.sync.aligned.m8n8.x4.trans.shared.b16 {%0,%1,%2,%3}, [%4];"
                 : "=r"(r[0]), "=r"(r[1]), "=r"(r[2]), "=r"(r[3]) : "r"(a));
}
__device__ __forceinline__ void mma16816(float* c, const uint32_t* a,
                                         uint32_t b0, uint32_t b1) {
    asm volatile(
        "mma.sync.aligned.m16n8k16.row.col.f32.bf16.bf16.f32 "
        "{%0,%1,%2,%3},{%4,%5,%6,%7},{%8,%9},{%0,%1,%2,%3};"
        : "+f"(c[0]), "+f"(c[1]), "+f"(c[2]), "+f"(c[3])
        : "r"(a[0]), "r"(a[1]), "r"(a[2]), "r"(a[3]), "r"(b0), "r"(b1));
}
#define CPA16(s, g) \
    asm volatile("cp.async.cg.shared.global [%0], [%1], 16;" :: "r"(s), "l"(g))
#define CPC()  asm volatile("cp.async.commit_group;" ::: "memory")
#define CPW0() asm volatile("cp.async.wait_group 0;" ::: "memory")
#define CPW1() asm volatile("cp.async.wait_group 1;" ::: "memory")
#define CPW2() asm volatile("cp.async.wait_group 2;" ::: "memory")

__device__ __forceinline__ uint32_t pkb(__nv_bfloat16 a, __nv_bfloat16 b) {
    return (uint32_t)__bfloat16_as_ushort(a) | ((uint32_t)__bfloat16_as_ushort(b) << 16);
}
__device__ __forceinline__ __nv_bfloat16 bfh(float v) { return __float2bfloat16_rn(v); }
__device__ __forceinline__ __nv_bfloat16 bfl(float v, __nv_bfloat16 h) {
    return __float2bfloat16_rn(v - __bfloat162float(h));
}

// ---------------------------------------------------------------------------
// prep: mask->u8, x->hi/lo, W->hi/lo (natural [k][n] layout)
// ---------------------------------------------------------------------------
__global__ void prep_mask(const float* __restrict__ m) {
    size_t i = (size_t)blockIdx.x * 256 + threadIdx.x;
    float4 v = ((const float4*)m)[i];
    ((uchar4*)g_m8)[i] = make_uchar4(v.x != 0.f, v.y != 0.f, v.z != 0.f, v.w != 0.f);
}
__device__ __forceinline__ void split_store(const float* src, __nv_bfloat16* dh,
                                            __nv_bfloat16* dl, size_t i) {
    float4 v = ((const float4*)src)[i];
    __nv_bfloat16 h0 = bfh(v.x), h1 = bfh(v.y), h2 = bfh(v.z), h3 = bfh(v.w);
    ((uint32_t*)dh)[2 * i]     = pkb(h0, h1);
    ((uint32_t*)dh)[2 * i + 1] = pkb(h2, h3);
    ((uint32_t*)dl)[2 * i]     = pkb(bfl(v.x, h0), bfl(v.y, h1));
    ((uint32_t*)dl)[2 * i + 1] = pkb(bfl(v.z, h2), bfl(v.w, h3));
}
__global__ void prep_x(const float* __restrict__ x) {
    split_store(x, g_xh, g_xl, (size_t)blockIdx.x * 256 + threadIdx.x);
}
__global__ void prep_w(const float* __restrict__ Wq, const float* __restrict__ Wk,
                       const float* __restrict__ Wv) {
    const float* W = blockIdx.y == 0 ? Wq : (blockIdx.y == 1 ? Wk : Wv);
    split_store(W, g_wh[blockIdx.y], g_wl[blockIdx.y],
                (size_t)blockIdx.x * 256 + threadIdx.x);
}

// ---------------------------------------------------------------------------
// QKV GEMM: C = X @ W (3x bf16-split HMMA). Block 128x128, 16 warps (4x4),
// warp tile 32x32, K-chunk 16, 4-stage cp.async pipeline + register-level
// fragment double buffering (LDSM of chunk c+1 overlaps MMAs of chunk c).
// Epilogue splits to [b,h,s,hd]; Q *= 1/8.
// Stage layout (bytes): Ah 0 (6144), Al 6144, Bh 12288 (4352), Bl 16640.
// ---------------------------------------------------------------------------
#define GST 20992
#define NSTG 4
__global__ __launch_bounds__(512, 1)
void qkv_gemm_hmma() {
    extern __shared__ __align__(16) char dsm[];

    const int tid = threadIdx.x, lane = tid & 31, wid = tid >> 5;
    const int wm = wid >> 2, wn = wid & 3;           // 4 x 4 warp grid
    const int z = blockIdx.z;
    const int m0 = blockIdx.y * 128, n0 = blockIdx.x * 128;
    const __nv_bfloat16* wh = g_wh[z];
    const __nv_bfloat16* wl = g_wl[z];

    // copy mapping: threads 0-255 copy hi (A+B), 256-511 copy lo.
    const int t2 = tid & 255;
    const int ar = t2 >> 1, ac = (t2 & 1) * 8;       // A: 128r x 16c
    const int br = t2 >> 4, bc = (t2 & 15) * 8;      // B: 16r x 128c
    const bool lo_half = (tid >= 256);
    const __nv_bfloat16* srcA = lo_half ? g_xl : g_xh;
    const __nv_bfloat16* srcB = lo_half ? wl : wh;
    const uint32_t dstA_off = (lo_half ? 6144u : 0u) + (uint32_t)(ar * 24 + ac) * 2;
    const uint32_t dstB_off = (lo_half ? 16640u : 12288u) + (uint32_t)(br * 136 + bc) * 2;
    const uint32_t sbase = smem_u32(dsm);

    auto preload = [&](int c, int st) {
        const int k0 = c * 16;
        const uint32_t s0 = sbase + st * GST;
        CPA16(s0 + dstA_off, srcA + (size_t)(m0 + ar) * ND + k0 + ac);
        CPA16(s0 + dstB_off, srcB + (size_t)(k0 + br) * ND + n0 + bc);
    };

    // Register fragment double buffers.
    uint32_t FAh[2][2][4], FAl[2][2][4], FBh[2][2][4], FBl[2][2][4];
    const uint32_t a_off =
        (uint32_t)((wm * 32 + (lane & 15)) * 24 + 8 * ((lane >> 4) & 1)) * 2;
    const uint32_t b_off =
        (uint32_t)((lane & 15) * 136 + wn * 32 + 8 * ((lane >> 4) & 1)) * 2;

    auto fragload = [&](int buf, int st) {
        const uint32_t sb = sbase + st * GST;
#pragma unroll
        for (int mt = 0; mt < 2; ++mt) {
            const uint32_t o = sb + a_off + (uint32_t)(mt * 16 * 24) * 2;
            ldsm4(FAh[buf][mt], o);
            ldsm4(FAl[buf][mt], o + 6144);
        }
#pragma unroll
        for (int ntp = 0; ntp < 2; ++ntp) {
            const uint32_t o = sb + 12288 + b_off + (uint32_t)(ntp * 16) * 2;
            ldsm4t(FBh[buf][ntp], o);
            ldsm4t(FBl[buf][ntp], o + 4352);
        }
    };

    float acc[2][4][4] = {};

    preload(0, 0); CPC();
    preload(1, 1); CPC();
    preload(2, 2); CPC();
    CPW2();
    __syncthreads();
    fragload(0, 0);

    for (int c = 0; c < 64; ++c) {
        const int cur = c & 1;
        if (c + 1 < 64) {
            CPW1();                       // chunk c+1 resident in smem
            __syncthreads();
            fragload(cur ^ 1, (c + 1) & (NSTG - 1));
            if (c + 3 < 64) preload(c + 3, (c + 3) & (NSTG - 1));
            CPC();
        }
        // hh sweep
#pragma unroll
        for (int mt = 0; mt < 2; ++mt)
#pragma unroll
            for (int ntp = 0; ntp < 2; ++ntp) {
                mma16816(acc[mt][2 * ntp],     FAh[cur][mt],
                         FBh[cur][ntp][0], FBh[cur][ntp][1]);
                mma16816(acc[mt][2 * ntp + 1], FAh[cur][mt],
                         FBh[cur][ntp][2], FBh[cur][ntp][3]);
            }
        // hl sweep
#pragma unroll
        for (int mt = 0; mt < 2; ++mt)
#pragma unroll
            for (int ntp = 0; ntp < 2; ++ntp) {
                mma16816(acc[mt][2 * ntp],     FAh[cur][mt],
                         FBl[cur][ntp][0], FBl[cur][ntp][1]);
                mma16816(acc[mt][2 * ntp + 1], FAh[cur][mt],
                         FBl[cur][ntp][2], FBl[cur][ntp][3]);
            }
        // lh sweep
#pragma unroll
        for (int mt = 0; mt < 2; ++mt)
#pragma unroll
            for (int ntp = 0; ntp < 2; ++ntp) {
                mma16816(acc[mt][2 * ntp],     FAl[cur][mt],
                         FBh[cur][ntp][0], FBh[cur][ntp][1]);
                mma16816(acc[mt][2 * ntp + 1], FAl[cur][mt],
                         FBh[cur][ntp][2], FBh[cur][ntp][3]);
            }
    }

    // Epilogue: split + scatter to [b,h,s,hd]
    __nv_bfloat16 *dh, *dl;
    if (z == 0)      { dh = g_qh; dl = g_ql; }
    else if (z == 1) { dh = g_kh; dl = g_kl; }
    else             { dh = g_vh; dl = g_vl; }
    const float scale = (z == 0) ? 0.125f : 1.0f;
    const int g = lane >> 2, lam = lane & 3;
#pragma unroll
    for (int mt = 0; mt < 2; ++mt)
#pragma unroll
        for (int nt = 0; nt < 4; ++nt) {
            const int n = n0 + wn * 32 + nt * 8 + lam * 2;
            const int h = n >> 6, hd = n & (NHD - 1);
#pragma unroll
            for (int rr = 0; rr < 2; ++rr) {
                const int m = m0 + wm * 32 + mt * 16 + g + rr * 8;
                const int b = m >> 10, s = m & (NS - 1);
                const float c0 = acc[mt][nt][rr * 2 + 0] * scale;
                const float c1 = acc[mt][nt][rr * 2 + 1] * scale;
                __nv_bfloat16 h0 = bfh(c0), h1 = bfh(c1);
                const size_t idx = (((size_t)b * NH + h) * NS + s) * NHD + hd;
                *(uint32_t*)(dh + idx) = pkb(h0, h1);
                *(uint32_t*)(dl + idx) = pkb(bfl(c0, h0), bfl(c1, h1));
            }
        }
}

// ---------------------------------------------------------------------------
// Fused attention (HMMA). Block = 64 q-rows x (h,b); 4 warps x 16 q-rows.
// Q frags direct from global; K/V stream in 32-key cp.async double buffer.
// ---------------------------------------------------------------------------
__global__ __launch_bounds__(128, 3)
void attn_tc(float* __restrict__ out) {
    __shared__ __nv_bfloat16 Ksh[2][32 * 72], Ksl[2][32 * 72];
    __shared__ __nv_bfloat16 Vsh[2][32 * 72], Vsl[2][32 * 72];

    const int tid = threadIdx.x, lane = tid & 31, wid = tid >> 5;
    const int qt = blockIdx.x, h = blockIdx.y, b = blockIdx.z;
    const size_t bh = (size_t)b * NH + h;
    const int g = lane >> 2, lam = lane & 3;

    const __nv_bfloat16* kh_g = g_kh + bh * NS * NHD;
    const __nv_bfloat16* kl_g = g_kl + bh * NS * NHD;
    const __nv_bfloat16* vh_g = g_vh + bh * NS * NHD;
    const __nv_bfloat16* vl_g = g_vl + bh * NS * NHD;

    uint32_t qfh[4][4], qfl[4][4];
    {
        const __nv_bfloat16* qh_g = g_qh + (bh * NS + (size_t)qt * 64) * NHD;
        const __nv_bfloat16* ql_g = g_ql + (bh * NS + (size_t)qt * 64) * NHD;
        const int r0 = wid * 16 + g, r1 = r0 + 8;
#pragma unroll
        for (int dt = 0; dt < 4; ++dt) {
            const int c = dt * 16 + lam * 2;
            qfh[dt][0] = *(const uint32_t*)(qh_g + (size_t)r0 * NHD + c);
            qfh[dt][1] = *(const uint32_t*)(qh_g + (size_t)r1 * NHD + c);
            qfh[dt][2] = *(const uint32_t*)(qh_g + (size_t)r0 * NHD + c + 8);
            qfh[dt][3] = *(const uint32_t*)(qh_g + (size_t)r1 * NHD + c + 8);
            qfl[dt][0] = *(const uint32_t*)(ql_g + (size_t)r0 * NHD + c);
            qfl[dt][1] = *(const uint32_t*)(ql_g + (size_t)r1 * NHD + c);
            qfl[dt][2] = *(const uint32_t*)(ql_g + (size_t)r0 * NHD + c + 8);
            qfl[dt][3] = *(const uint32_t*)(ql_g + (size_t)r1 * NHD + c + 8);
        }
    }

    auto preload = [&](int kt, int st) {
#pragma unroll
        for (int i = 0; i < 2; ++i) {
            const int idx = tid * 2 + i;
            const int r = idx >> 3, c8 = (idx & 7) * 8;
            const size_t gi = (size_t)(kt * 32 + r) * NHD + c8;
            const uint32_t so = smem_u32(&Ksh[st][r * 72 + c8]);
            const uint32_t d  = (uint32_t)((char*)Ksl - (char*)Ksh);
            const uint32_t dv = (uint32_t)((char*)Vsh - (char*)Ksh);
            const uint32_t dl2 = (uint32_t)((char*)Vsl - (char*)Ksh);
            CPA16(so,       kh_g + gi);
            CPA16(so + d,   kl_g + gi);
            CPA16(so + dv,  vh_g + gi);
            CPA16(so + dl2, vl_g + gi);
        }
    };

    float ctx[8][4] = {};
    float rs0 = 0.f, rs1 = 0.f;
    const int q0 = qt * 64 + wid * 16 + g;
    const uint8_t* mrow0 = g_m8 + ((size_t)b * NS + q0) * NS;
    const uint8_t* mrow1 = mrow0 + 8 * NS;

    preload(0, 0);
    CPC();

    for (int kts = 0; kts < 32; ++kts) {
        const int st = kts & 1;
        CPW0();
        __syncthreads();
        if (kts + 1 < 32) { preload(kts + 1, st ^ 1); CPC(); }

        float sacc[4][4] = {};
#pragma unroll
        for (int ntp = 0; ntp < 2; ++ntp) {
#pragma unroll
            for (int dt = 0; dt < 4; ++dt) {
                const uint32_t boff = smem_u32(
                    &Ksh[st][(ntp * 16 + 8 * ((lane >> 4) & 1) + (lane & 7)) * 72 +
                             dt * 16 + 8 * ((lane >> 3) & 1)]);
                uint32_t kb_h[4], kb_l[4];
                ldsm4(kb_h, boff);
                ldsm4(kb_l, boff + (uint32_t)((char*)Ksl - (char*)Ksh));
                float* s0 = sacc[2 * ntp];
                float* s1 = sacc[2 * ntp + 1];
                mma16816(s0, qfh[dt], kb_h[0], kb_h[1]);
                mma16816(s1, qfh[dt], kb_h[2], kb_h[3]);
                mma16816(s0, qfh[dt], kb_l[0], kb_l[1]);
                mma16816(s1, qfh[dt], kb_l[2], kb_l[3]);
                mma16816(s0, qfl[dt], kb_h[0], kb_h[1]);
                mma16816(s1, qfl[dt], kb_h[2], kb_h[3]);
            }
        }

        uint32_t pah[2][4], pal[2][4];
#pragma unroll
        for (int nt = 0; nt < 4; ++nt) {
            const int t = kts * 32 + nt * 8 + lam * 2;
            const uchar2 mc0 = *(const uchar2*)(mrow0 + t);
            const uchar2 mc1 = *(const uchar2*)(mrow1 + t);
            const float p0 = __expf(sacc[nt][0]) * (float)mc0.x;
            const float p1 = __expf(sacc[nt][1]) * (float)mc0.y;
            const float p2 = __expf(sacc[nt][2]) * (float)mc1.x;
            const float p3 = __expf(sacc[nt][3]) * (float)mc1.y;
            rs0 += p0 + p1;
            rs1 += p2 + p3;
            __nv_bfloat16 h0 = bfh(p0), h1 = bfh(p1), h2 = bfh(p2), h3 = bfh(p3);
            const int j = nt >> 1, o = (nt & 1) * 2;
            pah[j][o + 0] = pkb(h0, h1);
            pah[j][o + 1] = pkb(h2, h3);
            pal[j][o + 0] = pkb(bfl(p0, h0), bfl(p1, h1));
            pal[j][o + 1] = pkb(bfl(p2, h2), bfl(p3, h3));
        }

#pragma unroll
        for (int ntp = 0; ntp < 4; ++ntp) {
#pragma unroll
            for (int j = 0; j < 2; ++j) {
                const uint32_t voff = smem_u32(
                    &Vsh[st][(j * 16 + (lane & 15)) * 72 + ntp * 16 +
                             8 * ((lane >> 4) & 1)]);
                uint32_t vb_h[4], vb_l[4];
                ldsm4t(vb_h, voff);
                ldsm4t(vb_l, voff + (uint32_t)((char*)Vsl - (char*)Vsh));
                float* c0 = ctx[2 * ntp];
                float* c1 = ctx[2 * ntp + 1];
                mma16816(c0, pah[j], vb_h[0], vb_h[1]);
                mma16816(c1, pah[j], vb_h[2], vb_h[3]);
                mma16816(c0, pah[j], vb_l[0], vb_l[1]);
                mma16816(c1, pah[j], vb_l[2], vb_l[3]);
                mma16816(c0, pal[j], vb_h[0], vb_h[1]);
                mma16816(c1, pal[j], vb_h[2], vb_h[3]);
            }
        }
    }

    rs0 += __shfl_xor_sync(0xffffffffu, rs0, 1);
    rs0 += __shfl_xor_sync(0xffffffffu, rs0, 2);
    rs1 += __shfl_xor_sync(0xffffffffu, rs1, 1);
    rs1 += __shfl_xor_sync(0xffffffffu, rs1, 2);
    const float inv0 = 1.0f / (rs0 + 1e-8f);
    const float inv1 = 1.0f / (rs1 + 1e-8f);

#pragma unroll
    for (int nt = 0; nt < 8; ++nt) {
        const int d = nt * 8 + lam * 2;
        float* o0 = out + ((size_t)b * NS + q0) * ND + h * NHD + d;
        *(float2*)o0 = make_float2(ctx[nt][0] * inv0, ctx[nt][1] * inv0);
        *(float2*)(o0 + (size_t)8 * ND) =
            make_float2(ctx[nt][2] * inv1, ctx[nt][3] * inv1);
    }
}

// ---------------------------------------------------------------------------
extern "C" void kernel_launch(void* const* d_in, const int* in_sizes, int n_in,
                              void* d_out, int out_size) {
    (void)in_sizes; (void)n_in; (void)out_size;
    const float* x    = (const float*)d_in[0];
    const float* mask = (const float*)d_in[1];
    const float* Wq   = (const float*)d_in[2];
    const float* Wk   = (const float*)d_in[3];
    const float* Wv   = (const float*)d_in[4];
    float* out = (float*)d_out;

    cudaFuncSetAttribute(qkv_gemm_hmma,
                         cudaFuncAttributeMaxDynamicSharedMemorySize, NSTG * GST);

    prep_mask<<<(NB * NS * NS) / 1024, 256>>>(mask);
    prep_x<<<(NB * NS * ND) / 1024, 256>>>(x);
    prep_w<<<dim3((ND * ND) / 1024, 3), 256>>>(Wq, Wk, Wv);
    qkv_gemm_hmma<<<dim3(ND / 128, (NB * NS) / 128, 3), 512, NSTG * GST>>>();
    attn_tc<<<dim3(NS / 64, NH, NB), 128>>>(out);
}

// round 11
// speedup vs baseline: 1.2754x; 1.0990x over previous
#include <cuda_runtime.h>
#include <cuda_bf16.h>
#include <stdint.h>

#define NB 8
#define NS 1024
#define ND 1024
#define NH 16
#define NHD 64

// Static device scratch. bf16 hi/lo split operands. g_wh/g_wl natural [k][n].
static __device__ __align__(16) __nv_bfloat16 g_xh[(size_t)NB * NS * ND];
static __device__ __align__(16) __nv_bfloat16 g_xl[(size_t)NB * NS * ND];
static __device__ __align__(16) __nv_bfloat16 g_wh[3][(size_t)ND * ND];
static __device__ __align__(16) __nv_bfloat16 g_wl[3][(size_t)ND * ND];
static __device__ __align__(16) __nv_bfloat16 g_qh[(size_t)NB * NH * NS * NHD];
static __device__ __align__(16) __nv_bfloat16 g_ql[(size_t)NB * NH * NS * NHD];
static __device__ __align__(16) __nv_bfloat16 g_kh[(size_t)NB * NH * NS * NHD];
static __device__ __align__(16) __nv_bfloat16 g_kl[(size_t)NB * NH * NS * NHD];
static __device__ __align__(16) __nv_bfloat16 g_vh[(size_t)NB * NH * NS * NHD];
static __device__ __align__(16) __nv_bfloat16 g_vl[(size_t)NB * NH * NS * NHD];
static __device__ __align__(16) uint8_t       g_m8[(size_t)NB * NS * NS];

// ---------------------------------------------------------------------------
__device__ __forceinline__ uint32_t smem_u32(const void* p) {
    uint32_t a;
    asm("{ .reg .u64 t; cvta.to.shared.u64 t, %1; cvt.u32.u64 %0, t; }"
        : "=r"(a) : "l"(p));
    return a;
}
__device__ __forceinline__ void ldsm4(uint32_t* r, uint32_t a) {
    asm volatile("ldmatrix.sync.aligned.m8n8.x4.shared.b16 {%0,%1,%2,%3}, [%4];"
                 : "=r"(r[0]), "=r"(r[1]), "=r"(r[2]), "=r"(r[3]) : "r"(a));
}
__device__ __forceinline__ void ldsm4t(uint32_t* r, uint32_t a) {
    asm volatile("ldmatrix.sync.aligned.m8n8.x4.trans.shared.b16 {%0,%1,%2,%3}, [%4];"
                 : "=r"(r[0]), "=r"(r[1]), "=r"(r[2]), "=r"(r[3]) : "r"(a));
}
__device__ __forceinline__ void mma16816(float* c, const uint32_t* a,
                                         uint32_t b0, uint32_t b1) {
    asm volatile(
        "mma.sync.aligned.m16n8k16.row.col.f32.bf16.bf16.f32 "
        "{%0,%1,%2,%3},{%4,%5,%6,%7},{%8,%9},{%0,%1,%2,%3};"
        : "+f"(c[0]), "+f"(c[1]), "+f"(c[2]), "+f"(c[3])
        : "r"(a[0]), "r"(a[1]), "r"(a[2]), "r"(a[3]), "r"(b0), "r"(b1));
}
#define CPA16(s, g) \
    asm volatile("cp.async.cg.shared.global [%0], [%1], 16;" :: "r"(s), "l"(g))
#define CPC()  asm volatile("cp.async.commit_group;" ::: "memory")
#define CPW0() asm volatile("cp.async.wait_group 0;" ::: "memory")
#define CPW2() asm volatile("cp.async.wait_group 2;" ::: "memory")

__device__ __forceinline__ uint32_t pkb(__nv_bfloat16 a, __nv_bfloat16 b) {
    return (uint32_t)__bfloat16_as_ushort(a) | ((uint32_t)__bfloat16_as_ushort(b) << 16);
}
__device__ __forceinline__ __nv_bfloat16 bfh(float v) { return __float2bfloat16_rn(v); }
__device__ __forceinline__ __nv_bfloat16 bfl(float v, __nv_bfloat16 h) {
    return __float2bfloat16_rn(v - __bfloat162float(h));
}

// ---------------------------------------------------------------------------
// prep: mask->u8, x->hi/lo, W->hi/lo (natural [k][n] layout)
// ---------------------------------------------------------------------------
__global__ void prep_mask(const float* __restrict__ m) {
    size_t i = (size_t)blockIdx.x * 256 + threadIdx.x;
    float4 v = ((const float4*)m)[i];
    ((uchar4*)g_m8)[i] = make_uchar4(v.x != 0.f, v.y != 0.f, v.z != 0.f, v.w != 0.f);
}
__device__ __forceinline__ void split_store(const float* src, __nv_bfloat16* dh,
                                            __nv_bfloat16* dl, size_t i) {
    float4 v = ((const float4*)src)[i];
    __nv_bfloat16 h0 = bfh(v.x), h1 = bfh(v.y), h2 = bfh(v.z), h3 = bfh(v.w);
    ((uint32_t*)dh)[2 * i]     = pkb(h0, h1);
    ((uint32_t*)dh)[2 * i + 1] = pkb(h2, h3);
    ((uint32_t*)dl)[2 * i]     = pkb(bfl(v.x, h0), bfl(v.y, h1));
    ((uint32_t*)dl)[2 * i + 1] = pkb(bfl(v.z, h2), bfl(v.w, h3));
}
__global__ void prep_x(const float* __restrict__ x) {
    split_store(x, g_xh, g_xl, (size_t)blockIdx.x * 256 + threadIdx.x);
}
__global__ void prep_w(const float* __restrict__ Wq, const float* __restrict__ Wk,
                       const float* __restrict__ Wv) {
    const float* W = blockIdx.y == 0 ? Wq : (blockIdx.y == 1 ? Wk : Wv);
    split_store(W, g_wh[blockIdx.y], g_wl[blockIdx.y],
                (size_t)blockIdx.x * 256 + threadIdx.x);
}

// ---------------------------------------------------------------------------
// QKV GEMM: C = X @ W (3x bf16-split HMMA). Block 128x128, 16 warps (4x4),
// warp tile 32x32. K-chunk 32 (2 k-steps), 4-stage cp.async pipeline with
// commit-before-wait (2 chunks of slack after each wait) and register-level
// fragment double buffering at k-step granularity:
//   - kk=1 frags LDSM'd before kk=0's MMA sweep (same stage, no barrier)
//   - next chunk's kk=0 frags LDSM'd right after the per-chunk barrier
// One barrier per 32-K chunk (32 total, was 64).
// Stage layout (bytes): Ah 0 (10240 = 128x40 bf16), Al 10240,
//                       Bh 20480 (8704 = 32x136 bf16), Bl 29184. GST=37888.
// ---------------------------------------------------------------------------
#define GST 37888
#define NSTG 4
__global__ __launch_bounds__(512, 1)
void qkv_gemm_hmma() {
    extern __shared__ __align__(16) char dsm[];

    const int tid = threadIdx.x, lane = tid & 31, wid = tid >> 5;
    const int wm = wid >> 2, wn = wid & 3;           // 4 x 4 warp grid
    const int z = blockIdx.z;
    const int m0 = blockIdx.y * 128, n0 = blockIdx.x * 128;
    const __nv_bfloat16* wh = g_wh[z];
    const __nv_bfloat16* wl = g_wl[z];

    // copy mapping (each thread: 4x 16B = A hi, A lo, B hi, B lo)
    const int ar = tid >> 2, ac = (tid & 3) * 8;     // A: 128r x 32c
    const int br = tid >> 4, bc = (tid & 15) * 8;    // B: 32r x 128c
    const uint32_t dstA_off = (uint32_t)(ar * 40 + ac) * 2;
    const uint32_t dstB_off = 20480u + (uint32_t)(br * 136 + bc) * 2;
    const uint32_t sbase = smem_u32(dsm);

    auto preload = [&](int c, int st) {
        const int k0 = c * 32;
        const uint32_t s0 = sbase + st * GST;
        CPA16(s0 + dstA_off,          g_xh + (size_t)(m0 + ar) * ND + k0 + ac);
        CPA16(s0 + dstA_off + 10240,  g_xl + (size_t)(m0 + ar) * ND + k0 + ac);
        CPA16(s0 + dstB_off,          wh + (size_t)(k0 + br) * ND + n0 + bc);
        CPA16(s0 + dstB_off + 8704,   wl + (size_t)(k0 + br) * ND + n0 + bc);
    };

    // Register fragment double buffers (indexed by k-step parity).
    uint32_t FAh[2][2][4], FAl[2][2][4], FBh[2][2][4], FBl[2][2][4];
    const uint32_t a_base =
        (uint32_t)((wm * 32 + (lane & 15)) * 40 + 8 * ((lane >> 4) & 1)) * 2;
    const uint32_t b_base =
        (uint32_t)((lane & 15) * 136 + wn * 32 + 8 * ((lane >> 4) & 1)) * 2;

    auto fragload = [&](int buf, int st, int kk) {
        const uint32_t sb = sbase + st * GST;
        const uint32_t ao = sb + a_base + (uint32_t)(kk * 16) * 2;
        const uint32_t bo = sb + 20480 + b_base + (uint32_t)(kk * 16 * 136) * 2;
#pragma unroll
        for (int mt = 0; mt < 2; ++mt) {
            const uint32_t o = ao + (uint32_t)(mt * 16 * 40) * 2;
            ldsm4(FAh[buf][mt], o);
            ldsm4(FAl[buf][mt], o + 10240);
        }
#pragma unroll
        for (int ntp = 0; ntp < 2; ++ntp) {
            const uint32_t o = bo + (uint32_t)(ntp * 16) * 2;
            ldsm4t(FBh[buf][ntp], o);
            ldsm4t(FBl[buf][ntp], o + 8704);
        }
    };

    float acc[2][4][4] = {};

    auto sweeps = [&](int buf) {
        // hh sweep
#pragma unroll
        for (int mt = 0; mt < 2; ++mt)
#pragma unroll
            for (int ntp = 0; ntp < 2; ++ntp) {
                mma16816(acc[mt][2 * ntp],     FAh[buf][mt],
                         FBh[buf][ntp][0], FBh[buf][ntp][1]);
                mma16816(acc[mt][2 * ntp + 1], FAh[buf][mt],
                         FBh[buf][ntp][2], FBh[buf][ntp][3]);
            }
        // hl sweep
#pragma unroll
        for (int mt = 0; mt < 2; ++mt)
#pragma unroll
            for (int ntp = 0; ntp < 2; ++ntp) {
                mma16816(acc[mt][2 * ntp],     FAh[buf][mt],
                         FBl[buf][ntp][0], FBl[buf][ntp][1]);
                mma16816(acc[mt][2 * ntp + 1], FAh[buf][mt],
                         FBl[buf][ntp][2], FBl[buf][ntp][3]);
            }
        // lh sweep
#pragma unroll
        for (int mt = 0; mt < 2; ++mt)
#pragma unroll
            for (int ntp = 0; ntp < 2; ++ntp) {
                mma16816(acc[mt][2 * ntp],     FAl[buf][mt],
                         FBh[buf][ntp][0], FBh[buf][ntp][1]);
                mma16816(acc[mt][2 * ntp + 1], FAl[buf][mt],
                         FBh[buf][ntp][2], FBh[buf][ntp][3]);
            }
    };

    preload(0, 0); CPC();
    preload(1, 1); CPC();
    preload(2, 2); CPC();
    CPW2();                 // chunk 0 resident (pending: 1, 2)
    __syncthreads();
    fragload(0, 0, 0);

    for (int c = 0; c < 32; ++c) {
        const int st = c & (NSTG - 1);
        fragload(1, st, 1);          // kk=1 frags; same stage, no barrier needed
        sweeps(0);                   // kk=0 MMAs
        if (c + 1 < 32) {
            // stage (c+3)%4 == (c-1)%4 is dead for ALL warps (post barrier c-1)
            if (c + 3 < 32) { preload(c + 3, (c + 3) & (NSTG - 1)); CPC(); }
            CPW2();                  // guarantee chunk c+1 resident
            __syncthreads();
            fragload(0, (c + 1) & (NSTG - 1), 0);
        }
        sweeps(1);                   // kk=1 MMAs
    }

    // Epilogue: split + scatter to [b,h,s,hd]
    __nv_bfloat16 *dh, *dl;
    if (z == 0)      { dh = g_qh; dl = g_ql; }
    else if (z == 1) { dh = g_kh; dl = g_kl; }
    else             { dh = g_vh; dl = g_vl; }
    const float scale = (z == 0) ? 0.125f : 1.0f;
    const int g = lane >> 2, lam = lane & 3;
#pragma unroll
    for (int mt = 0; mt < 2; ++mt)
#pragma unroll
        for (int nt = 0; nt < 4; ++nt) {
            const int n = n0 + wn * 32 + nt * 8 + lam * 2;
            const int h = n >> 6, hd = n & (NHD - 1);
#pragma unroll
            for (int rr = 0; rr < 2; ++rr) {
                const int m = m0 + wm * 32 + mt * 16 + g + rr * 8;
                const int b = m >> 10, s = m & (NS - 1);
                const float c0 = acc[mt][nt][rr * 2 + 0] * scale;
                const float c1 = acc[mt][nt][rr * 2 + 1] * scale;
                __nv_bfloat16 h0 = bfh(c0), h1 = bfh(c1);
                const size_t idx = (((size_t)b * NH + h) * NS + s) * NHD + hd;
                *(uint32_t*)(dh + idx) = pkb(h0, h1);
                *(uint32_t*)(dl + idx) = pkb(bfl(c0, h0), bfl(c1, h1));
            }
        }
}

// ---------------------------------------------------------------------------
// Fused attention (HMMA, unchanged). Block = 64 q-rows x (h,b); 4 warps.
// ---------------------------------------------------------------------------
__global__ __launch_bounds__(128, 3)
void attn_tc(float* __restrict__ out) {
    __shared__ __nv_bfloat16 Ksh[2][32 * 72], Ksl[2][32 * 72];
    __shared__ __nv_bfloat16 Vsh[2][32 * 72], Vsl[2][32 * 72];

    const int tid = threadIdx.x, lane = tid & 31, wid = tid >> 5;
    const int qt = blockIdx.x, h = blockIdx.y, b = blockIdx.z;
    const size_t bh = (size_t)b * NH + h;
    const int g = lane >> 2, lam = lane & 3;

    const __nv_bfloat16* kh_g = g_kh + bh * NS * NHD;
    const __nv_bfloat16* kl_g = g_kl + bh * NS * NHD;
    const __nv_bfloat16* vh_g = g_vh + bh * NS * NHD;
    const __nv_bfloat16* vl_g = g_vl + bh * NS * NHD;

    uint32_t qfh[4][4], qfl[4][4];
    {
        const __nv_bfloat16* qh_g = g_qh + (bh * NS + (size_t)qt * 64) * NHD;
        const __nv_bfloat16* ql_g = g_ql + (bh * NS + (size_t)qt * 64) * NHD;
        const int r0 = wid * 16 + g, r1 = r0 + 8;
#pragma unroll
        for (int dt = 0; dt < 4; ++dt) {
            const int c = dt * 16 + lam * 2;
            qfh[dt][0] = *(const uint32_t*)(qh_g + (size_t)r0 * NHD + c);
            qfh[dt][1] = *(const uint32_t*)(qh_g + (size_t)r1 * NHD + c);
            qfh[dt][2] = *(const uint32_t*)(qh_g + (size_t)r0 * NHD + c + 8);
            qfh[dt][3] = *(const uint32_t*)(qh_g + (size_t)r1 * NHD + c + 8);
            qfl[dt][0] = *(const uint32_t*)(ql_g + (size_t)r0 * NHD + c);
            qfl[dt][1] = *(const uint32_t*)(ql_g + (size_t)r1 * NHD + c);
            qfl[dt][2] = *(const uint32_t*)(ql_g + (size_t)r0 * NHD + c + 8);
            qfl[dt][3] = *(const uint32_t*)(ql_g + (size_t)r1 * NHD + c + 8);
        }
    }

    auto preload = [&](int kt, int st) {
#pragma unroll
        for (int i = 0; i < 2; ++i) {
            const int idx = tid * 2 + i;
            const int r = idx >> 3, c8 = (idx & 7) * 8;
            const size_t gi = (size_t)(kt * 32 + r) * NHD + c8;
            const uint32_t so = smem_u32(&Ksh[st][r * 72 + c8]);
            const uint32_t d  = (uint32_t)((char*)Ksl - (char*)Ksh);
            const uint32_t dv = (uint32_t)((char*)Vsh - (char*)Ksh);
            const uint32_t dl2 = (uint32_t)((char*)Vsl - (char*)Ksh);
            CPA16(so,       kh_g + gi);
            CPA16(so + d,   kl_g + gi);
            CPA16(so + dv,  vh_g + gi);
            CPA16(so + dl2, vl_g + gi);
        }
    };

    float ctx[8][4] = {};
    float rs0 = 0.f, rs1 = 0.f;
    const int q0 = qt * 64 + wid * 16 + g;
    const uint8_t* mrow0 = g_m8 + ((size_t)b * NS + q0) * NS;
    const uint8_t* mrow1 = mrow0 + 8 * NS;

    preload(0, 0);
    CPC();

    for (int kts = 0; kts < 32; ++kts) {
        const int st = kts & 1;
        CPW0();
        __syncthreads();
        if (kts + 1 < 32) { preload(kts + 1, st ^ 1); CPC(); }

        float sacc[4][4] = {};
#pragma unroll
        for (int ntp = 0; ntp < 2; ++ntp) {
#pragma unroll
            for (int dt = 0; dt < 4; ++dt) {
                const uint32_t boff = smem_u32(
                    &Ksh[st][(ntp * 16 + 8 * ((lane >> 4) & 1) + (lane & 7)) * 72 +
                             dt * 16 + 8 * ((lane >> 3) & 1)]);
                uint32_t kb_h[4], kb_l[4];
                ldsm4(kb_h, boff);
                ldsm4(kb_l, boff + (uint32_t)((char*)Ksl - (char*)Ksh));
                float* s0 = sacc[2 * ntp];
                float* s1 = sacc[2 * ntp + 1];
                mma16816(s0, qfh[dt], kb_h[0], kb_h[1]);
                mma16816(s1, qfh[dt], kb_h[2], kb_h[3]);
                mma16816(s0, qfh[dt], kb_l[0], kb_l[1]);
                mma16816(s1, qfh[dt], kb_l[2], kb_l[3]);
                mma16816(s0, qfl[dt], kb_h[0], kb_h[1]);
                mma16816(s1, qfl[dt], kb_h[2], kb_h[3]);
            }
        }

        uint32_t pah[2][4], pal[2][4];
#pragma unroll
        for (int nt = 0; nt < 4; ++nt) {
            const int t = kts * 32 + nt * 8 + lam * 2;
            const uchar2 mc0 = *(const uchar2*)(mrow0 + t);
            const uchar2 mc1 = *(const uchar2*)(mrow1 + t);
            const float p0 = __expf(sacc[nt][0]) * (float)mc0.x;
            const float p1 = __expf(sacc[nt][1]) * (float)mc0.y;
            const float p2 = __expf(sacc[nt][2]) * (float)mc1.x;
            const float p3 = __expf(sacc[nt][3]) * (float)mc1.y;
            rs0 += p0 + p1;
            rs1 += p2 + p3;
            __nv_bfloat16 h0 = bfh(p0), h1 = bfh(p1), h2 = bfh(p2), h3 = bfh(p3);
            const int j = nt >> 1, o = (nt & 1) * 2;
            pah[j][o + 0] = pkb(h0, h1);
            pah[j][o + 1] = pkb(h2, h3);
            pal[j][o + 0] = pkb(bfl(p0, h0), bfl(p1, h1));
            pal[j][o + 1] = pkb(bfl(p2, h2), bfl(p3, h3));
        }

#pragma unroll
        for (int ntp = 0; ntp < 4; ++ntp) {
#pragma unroll
            for (int j = 0; j < 2; ++j) {
                const uint32_t voff = smem_u32(
                    &Vsh[st][(j * 16 + (lane & 15)) * 72 + ntp * 16 +
                             8 * ((lane >> 4) & 1)]);
                uint32_t vb_h[4], vb_l[4];
                ldsm4t(vb_h, voff);
                ldsm4t(vb_l, voff + (uint32_t)((char*)Vsl - (char*)Vsh));
                float* c0 = ctx[2 * ntp];
                float* c1 = ctx[2 * ntp + 1];
                mma16816(c0, pah[j], vb_h[0], vb_h[1]);
                mma16816(c1, pah[j], vb_h[2], vb_h[3]);
                mma16816(c0, pah[j], vb_l[0], vb_l[1]);
                mma16816(c1, pah[j], vb_l[2], vb_l[3]);
                mma16816(c0, pal[j], vb_h[0], vb_h[1]);
                mma16816(c1, pal[j], vb_h[2], vb_h[3]);
            }
        }
    }

    rs0 += __shfl_xor_sync(0xffffffffu, rs0, 1);
    rs0 += __shfl_xor_sync(0xffffffffu, rs0, 2);
    rs1 += __shfl_xor_sync(0xffffffffu, rs1, 1);
    rs1 += __shfl_xor_sync(0xffffffffu, rs1, 2);
    const float inv0 = 1.0f / (rs0 + 1e-8f);
    const float inv1 = 1.0f / (rs1 + 1e-8f);

#pragma unroll
    for (int nt = 0; nt < 8; ++nt) {
        const int d = nt * 8 + lam * 2;
        float* o0 = out + ((size_t)b * NS + q0) * ND + h * NHD + d;
        *(float2*)o0 = make_float2(ctx[nt][0] * inv0, ctx[nt][1] * inv0);
        *(float2*)(o0 + (size_t)8 * ND) =
            make_float2(ctx[nt][2] * inv1, ctx[nt][3] * inv1);
    }
}

// ---------------------------------------------------------------------------
extern "C" void kernel_launch(void* const* d_in, const int* in_sizes, int n_in,
                              void* d_out, int out_size) {
    (void)in_sizes; (void)n_in; (void)out_size;
    const float* x    = (const float*)d_in[0];
    const float* mask = (const float*)d_in[1];
    const float* Wq   = (const float*)d_in[2];
    const float* Wk   = (const float*)d_in[3];
    const float* Wv   = (const float*)d_in[4];
    float* out = (float*)d_out;

    cudaFuncSetAttribute(qkv_gemm_hmma,
                         cudaFuncAttributeMaxDynamicSharedMemorySize, NSTG * GST);

    prep_mask<<<(NB * NS * NS) / 1024, 256>>>(mask);
    prep_x<<<(NB * NS * ND) / 1024, 256>>>(x);
    prep_w<<<dim3((ND * ND) / 1024, 3), 256>>>(Wq, Wk, Wv);
    qkv_gemm_hmma<<<dim3(ND / 128, (NB * NS) / 128, 3), 512, NSTG * GST>>>();
    attn_tc<<<dim3(NS / 64, NH, NB), 128>>>(out);
}

// round 13
// speedup vs baseline: 1.2857x; 1.0081x over previous
#include <cuda_runtime.h>
#include <cuda_bf16.h>
#include <stdint.h>

#define NB 8
#define NS 1024
#define ND 1024
#define NH 16
#define NHD 64

// Static device scratch. bf16 hi/lo split operands. g_wh/g_wl natural [k][n].
static __device__ __align__(16) __nv_bfloat16 g_xh[(size_t)NB * NS * ND];
static __device__ __align__(16) __nv_bfloat16 g_xl[(size_t)NB * NS * ND];
static __device__ __align__(16) __nv_bfloat16 g_wh[3][(size_t)ND * ND];
static __device__ __align__(16) __nv_bfloat16 g_wl[3][(size_t)ND * ND];
static __device__ __align__(16) __nv_bfloat16 g_qh[(size_t)NB * NH * NS * NHD];
static __device__ __align__(16) __nv_bfloat16 g_ql[(size_t)NB * NH * NS * NHD];
static __device__ __align__(16) __nv_bfloat16 g_kh[(size_t)NB * NH * NS * NHD];
static __device__ __align__(16) __nv_bfloat16 g_kl[(size_t)NB * NH * NS * NHD];
static __device__ __align__(16) __nv_bfloat16 g_vh[(size_t)NB * NH * NS * NHD];
static __device__ __align__(16) __nv_bfloat16 g_vl[(size_t)NB * NH * NS * NHD];
static __device__ __align__(16) uint8_t       g_m8[(size_t)NB * NS * NS];

// ---------------------------------------------------------------------------
__device__ __forceinline__ uint32_t smem_u32(const void* p) {
    uint32_t a;
    asm("{ .reg .u64 t; cvta.to.shared.u64 t, %1; cvt.u32.u64 %0, t; }"
        : "=r"(a) : "l"(p));
    return a;
}
__device__ __forceinline__ void ldsm4(uint32_t* r, uint32_t a) {
    asm volatile("ldmatrix.sync.aligned.m8n8.x4.shared.b16 {%0,%1,%2,%3}, [%4];"
                 : "=r"(r[0]), "=r"(r[1]), "=r"(r[2]), "=r"(r[3]) : "r"(a));
}
__device__ __forceinline__ void ldsm4t(uint32_t* r, uint32_t a) {
    asm volatile("ldmatrix.sync.aligned.m8n8.x4.trans.shared.b16 {%0,%1,%2,%3}, [%4];"
                 : "=r"(r[0]), "=r"(r[1]), "=r"(r[2]), "=r"(r[3]) : "r"(a));
}
__device__ __forceinline__ void mma16816(float* c, const uint32_t* a,
                                         uint32_t b0, uint32_t b1) {
    asm volatile(
        "mma.sync.aligned.m16n8k16.row.col.f32.bf16.bf16.f32 "
        "{%0,%1,%2,%3},{%4,%5,%6,%7},{%8,%9},{%0,%1,%2,%3};"
        : "+f"(c[0]), "+f"(c[1]), "+f"(c[2]), "+f"(c[3])
        : "r"(a[0]), "r"(a[1]), "r"(a[2]), "r"(a[3]), "r"(b0), "r"(b1));
}
#define CPA16(s, g) \
    asm volatile("cp.async.cg.shared.global [%0], [%1], 16;" :: "r"(s), "l"(g))
#define CPC()  asm volatile("cp.async.commit_group;" ::: "memory")
#define CPW1() asm volatile("cp.async.wait_group 1;" ::: "memory")
#define CPW2() asm volatile("cp.async.wait_group 2;" ::: "memory")

__device__ __forceinline__ uint32_t pkb(__nv_bfloat16 a, __nv_bfloat16 b) {
    return (uint32_t)__bfloat16_as_ushort(a) | ((uint32_t)__bfloat16_as_ushort(b) << 16);
}
__device__ __forceinline__ __nv_bfloat16 bfh(float v) { return __float2bfloat16_rn(v); }
__device__ __forceinline__ __nv_bfloat16 bfl(float v, __nv_bfloat16 h) {
    return __float2bfloat16_rn(v - __bfloat162float(h));
}

// ---------------------------------------------------------------------------
// prep: mask->u8, x->hi/lo, W->hi/lo (natural [k][n] layout)
// ---------------------------------------------------------------------------
__global__ void prep_mask(const float* __restrict__ m) {
    size_t i = (size_t)blockIdx.x * 256 + threadIdx.x;
    float4 v = ((const float4*)m)[i];
    ((uchar4*)g_m8)[i] = make_uchar4(v.x != 0.f, v.y != 0.f, v.z != 0.f, v.w != 0.f);
}
__device__ __forceinline__ void split_store(const float* src, __nv_bfloat16* dh,
                                            __nv_bfloat16* dl, size_t i) {
    float4 v = ((const float4*)src)[i];
    __nv_bfloat16 h0 = bfh(v.x), h1 = bfh(v.y), h2 = bfh(v.z), h3 = bfh(v.w);
    ((uint32_t*)dh)[2 * i]     = pkb(h0, h1);
    ((uint32_t*)dh)[2 * i + 1] = pkb(h2, h3);
    ((uint32_t*)dl)[2 * i]     = pkb(bfl(v.x, h0), bfl(v.y, h1));
    ((uint32_t*)dl)[2 * i + 1] = pkb(bfl(v.z, h2), bfl(v.w, h3));
}
__global__ void prep_x(const float* __restrict__ x) {
    split_store(x, g_xh, g_xl, (size_t)blockIdx.x * 256 + threadIdx.x);
}
__global__ void prep_w(const float* __restrict__ Wq, const float* __restrict__ Wk,
                       const float* __restrict__ Wv) {
    const float* W = blockIdx.y == 0 ? Wq : (blockIdx.y == 1 ? Wk : Wv);
    split_store(W, g_wh[blockIdx.y], g_wl[blockIdx.y],
                (size_t)blockIdx.x * 256 + threadIdx.x);
}

// ---------------------------------------------------------------------------
// QKV GEMM (unchanged from round 10): 128x128 block, 16 warps (4x4), 32x32
// warp tile, K-chunk 32, 4-stage cp.async with commit-before-wait, k-step
// register double buffering. One barrier per 32-K chunk.
// ---------------------------------------------------------------------------
#define GST 37888
#define NSTG 4
__global__ __launch_bounds__(512, 1)
void qkv_gemm_hmma() {
    extern __shared__ __align__(16) char dsm[];

    const int tid = threadIdx.x, lane = tid & 31, wid = tid >> 5;
    const int wm = wid >> 2, wn = wid & 3;
    const int z = blockIdx.z;
    const int m0 = blockIdx.y * 128, n0 = blockIdx.x * 128;
    const __nv_bfloat16* wh = g_wh[z];
    const __nv_bfloat16* wl = g_wl[z];

    const int ar = tid >> 2, ac = (tid & 3) * 8;
    const int br = tid >> 4, bc = (tid & 15) * 8;
    const uint32_t dstA_off = (uint32_t)(ar * 40 + ac) * 2;
    const uint32_t dstB_off = 20480u + (uint32_t)(br * 136 + bc) * 2;
    const uint32_t sbase = smem_u32(dsm);

    auto preload = [&](int c, int st) {
        const int k0 = c * 32;
        const uint32_t s0 = sbase + st * GST;
        CPA16(s0 + dstA_off,          g_xh + (size_t)(m0 + ar) * ND + k0 + ac);
        CPA16(s0 + dstA_off + 10240,  g_xl + (size_t)(m0 + ar) * ND + k0 + ac);
        CPA16(s0 + dstB_off,          wh + (size_t)(k0 + br) * ND + n0 + bc);
        CPA16(s0 + dstB_off + 8704,   wl + (size_t)(k0 + br) * ND + n0 + bc);
    };

    uint32_t FAh[2][2][4], FAl[2][2][4], FBh[2][2][4], FBl[2][2][4];
    const uint32_t a_base =
        (uint32_t)((wm * 32 + (lane & 15)) * 40 + 8 * ((lane >> 4) & 1)) * 2;
    const uint32_t b_base =
        (uint32_t)((lane & 15) * 136 + wn * 32 + 8 * ((lane >> 4) & 1)) * 2;

    auto fragload = [&](int buf, int st, int kk) {
        const uint32_t sb = sbase + st * GST;
        const uint32_t ao = sb + a_base + (uint32_t)(kk * 16) * 2;
        const uint32_t bo = sb + 20480 + b_base + (uint32_t)(kk * 16 * 136) * 2;
#pragma unroll
        for (int mt = 0; mt < 2; ++mt) {
            const uint32_t o = ao + (uint32_t)(mt * 16 * 40) * 2;
            ldsm4(FAh[buf][mt], o);
            ldsm4(FAl[buf][mt], o + 10240);
        }
#pragma unroll
        for (int ntp = 0; ntp < 2; ++ntp) {
            const uint32_t o = bo + (uint32_t)(ntp * 16) * 2;
            ldsm4t(FBh[buf][ntp], o);
            ldsm4t(FBl[buf][ntp], o + 8704);
        }
    };

    float acc[2][4][4] = {};

    auto sweeps = [&](int buf) {
#pragma unroll
        for (int mt = 0; mt < 2; ++mt)
#pragma unroll
            for (int ntp = 0; ntp < 2; ++ntp) {
                mma16816(acc[mt][2 * ntp],     FAh[buf][mt],
                         FBh[buf][ntp][0], FBh[buf][ntp][1]);
                mma16816(acc[mt][2 * ntp + 1], FAh[buf][mt],
                         FBh[buf][ntp][2], FBh[buf][ntp][3]);
            }
#pragma unroll
        for (int mt = 0; mt < 2; ++mt)
#pragma unroll
            for (int ntp = 0; ntp < 2; ++ntp) {
                mma16816(acc[mt][2 * ntp],     FAh[buf][mt],
                         FBl[buf][ntp][0], FBl[buf][ntp][1]);
                mma16816(acc[mt][2 * ntp + 1], FAh[buf][mt],
                         FBl[buf][ntp][2], FBl[buf][ntp][3]);
            }
#pragma unroll
        for (int mt = 0; mt < 2; ++mt)
#pragma unroll
            for (int ntp = 0; ntp < 2; ++ntp) {
                mma16816(acc[mt][2 * ntp],     FAl[buf][mt],
                         FBh[buf][ntp][0], FBh[buf][ntp][1]);
                mma16816(acc[mt][2 * ntp + 1], FAl[buf][mt],
                         FBh[buf][ntp][2], FBh[buf][ntp][3]);
            }
    };

    preload(0, 0); CPC();
    preload(1, 1); CPC();
    preload(2, 2); CPC();
    CPW2();
    __syncthreads();
    fragload(0, 0, 0);

    for (int c = 0; c < 32; ++c) {
        const int st = c & (NSTG - 1);
        fragload(1, st, 1);
        sweeps(0);
        if (c + 1 < 32) {
            if (c + 3 < 32) { preload(c + 3, (c + 3) & (NSTG - 1)); CPC(); }
            CPW2();
            __syncthreads();
            fragload(0, (c + 1) & (NSTG - 1), 0);
        }
        sweeps(1);
    }

    __nv_bfloat16 *dh, *dl;
    if (z == 0)      { dh = g_qh; dl = g_ql; }
    else if (z == 1) { dh = g_kh; dl = g_kl; }
    else             { dh = g_vh; dl = g_vl; }
    const float scale = (z == 0) ? 0.125f : 1.0f;
    const int g = lane >> 2, lam = lane & 3;
#pragma unroll
    for (int mt = 0; mt < 2; ++mt)
#pragma unroll
        for (int nt = 0; nt < 4; ++nt) {
            const int n = n0 + wn * 32 + nt * 8 + lam * 2;
            const int h = n >> 6, hd = n & (NHD - 1);
#pragma unroll
            for (int rr = 0; rr < 2; ++rr) {
                const int m = m0 + wm * 32 + mt * 16 + g + rr * 8;
                const int b = m >> 10, s = m & (NS - 1);
                const float c0 = acc[mt][nt][rr * 2 + 0] * scale;
                const float c1 = acc[mt][nt][rr * 2 + 1] * scale;
                __nv_bfloat16 h0 = bfh(c0), h1 = bfh(c1);
                const size_t idx = (((size_t)b * NH + h) * NS + s) * NHD + hd;
                *(uint32_t*)(dh + idx) = pkb(h0, h1);
                *(uint32_t*)(dl + idx) = pkb(bfl(c0, h0), bfl(c1, h1));
            }
        }
}

// ---------------------------------------------------------------------------
// Fused attention (HMMA). Block = 128 q-rows x (h,b); 4 warps x 32 q-rows
// (mt = two 16-row halves share every K/V fragment -> LDSM:MMA = 1:3).
// 3-stage cp.async ring in dynamic smem (stage = Kh|Kl|Vh|Vl, 4x4608 B).
// Per-accumulator MMA order identical to prior rounds (bitwise canary).
// ---------------------------------------------------------------------------
#define AST 18432
#define AKL 4608
__global__ __launch_bounds__(128)
void attn_tc(float* __restrict__ out) {
    extern __shared__ __align__(16) char asm_[];

    const int tid = threadIdx.x, lane = tid & 31, wid = tid >> 5;
    const int qt = blockIdx.x, h = blockIdx.y, b = blockIdx.z;
    const size_t bh = (size_t)b * NH + h;
    const int g = lane >> 2, lam = lane & 3;
    const uint32_t sb = smem_u32(asm_);

    const __nv_bfloat16* kh_g = g_kh + bh * NS * NHD;
    const __nv_bfloat16* kl_g = g_kl + bh * NS * NHD;
    const __nv_bfloat16* vh_g = g_vh + bh * NS * NHD;
    const __nv_bfloat16* vl_g = g_vl + bh * NS * NHD;

    const int base_q = qt * 128 + wid * 32;

    // Q fragments straight from global (frag layout == memory layout).
    uint32_t qfh[2][4][4], qfl[2][4][4];
    {
        const __nv_bfloat16* qh_g = g_qh + (bh * NS + (size_t)base_q) * NHD;
        const __nv_bfloat16* ql_g = g_ql + (bh * NS + (size_t)base_q) * NHD;
#pragma unroll
        for (int mt = 0; mt < 2; ++mt) {
            const int r0 = mt * 16 + g, r1 = r0 + 8;
#pragma unroll
            for (int dt = 0; dt < 4; ++dt) {
                const int c = dt * 16 + lam * 2;
                qfh[mt][dt][0] = *(const uint32_t*)(qh_g + (size_t)r0 * NHD + c);
                qfh[mt][dt][1] = *(const uint32_t*)(qh_g + (size_t)r1 * NHD + c);
                qfh[mt][dt][2] = *(const uint32_t*)(qh_g + (size_t)r0 * NHD + c + 8);
                qfh[mt][dt][3] = *(const uint32_t*)(qh_g + (size_t)r1 * NHD + c + 8);
                qfl[mt][dt][0] = *(const uint32_t*)(ql_g + (size_t)r0 * NHD + c);
                qfl[mt][dt][1] = *(const uint32_t*)(ql_g + (size_t)r1 * NHD + c);
                qfl[mt][dt][2] = *(const uint32_t*)(ql_g + (size_t)r0 * NHD + c + 8);
                qfl[mt][dt][3] = *(const uint32_t*)(ql_g + (size_t)r1 * NHD + c + 8);
            }
        }
    }

    // cp.async: stage holds 32 keys x 64 cols x {Kh,Kl,Vh,Vl}; 2x16B/thread ea.
    auto preload = [&](int kt, int st) {
#pragma unroll
        for (int i = 0; i < 2; ++i) {
            const int idx = tid * 2 + i;
            const int r = idx >> 3, c8 = (idx & 7) * 8;
            const size_t gi = (size_t)(kt * 32 + r) * NHD + c8;
            const uint32_t so = sb + st * AST + (uint32_t)(r * 72 + c8) * 2;
            CPA16(so,           kh_g + gi);
            CPA16(so + AKL,     kl_g + gi);
            CPA16(so + 2 * AKL, vh_g + gi);
            CPA16(so + 3 * AKL, vl_g + gi);
        }
    };

    float ctx[2][8][4] = {};
    float rs[2][2] = {};
    const uint8_t* mr0 = g_m8 + ((size_t)b * NS + base_q + g) * NS;  // +mt*16, +8

    preload(0, 0); CPC();
    preload(1, 1); CPC();

    for (int kts = 0; kts < 32; ++kts) {
        const int st = kts % 3;
        CPW1();
        __syncthreads();
        if (kts + 2 < 32) { preload(kts + 2, (kts + 2) % 3); CPC(); }

        const uint32_t stb = sb + st * AST;

        // S = Q K^T : K frags loaded once, reused by both q-halves.
        float sacc[2][4][4] = {};
#pragma unroll
        for (int ntp = 0; ntp < 2; ++ntp) {
#pragma unroll
            for (int dt = 0; dt < 4; ++dt) {
                const uint32_t boff = stb +
                    (uint32_t)((ntp * 16 + 8 * ((lane >> 4) & 1) + (lane & 7)) * 72 +
                               dt * 16 + 8 * ((lane >> 3) & 1)) * 2;
                uint32_t kb_h[4], kb_l[4];
                ldsm4(kb_h, boff);
                ldsm4(kb_l, boff + AKL);
#pragma unroll
                for (int mt = 0; mt < 2; ++mt) {
                    float* s0 = sacc[mt][2 * ntp];
                    float* s1 = sacc[mt][2 * ntp + 1];
                    mma16816(s0, qfh[mt][dt], kb_h[0], kb_h[1]);
                    mma16816(s1, qfh[mt][dt], kb_h[2], kb_h[3]);
                    mma16816(s0, qfh[mt][dt], kb_l[0], kb_l[1]);
                    mma16816(s1, qfh[mt][dt], kb_l[2], kb_l[3]);
                    mma16816(s0, qfl[mt][dt], kb_h[0], kb_h[1]);
                    mma16816(s1, qfl[mt][dt], kb_h[2], kb_h[3]);
                }
            }
        }

        // P = exp(S)*mask -> split A-fragments (registers only)
        uint32_t pah[2][2][4], pal[2][2][4];
#pragma unroll
        for (int mt = 0; mt < 2; ++mt) {
            const uint8_t* m0p = mr0 + (size_t)(mt * 16) * NS;
            const uint8_t* m1p = m0p + (size_t)8 * NS;
#pragma unroll
            for (int nt = 0; nt < 4; ++nt) {
                const int t = kts * 32 + nt * 8 + lam * 2;
                const uchar2 mc0 = *(const uchar2*)(m0p + t);
                const uchar2 mc1 = *(const uchar2*)(m1p + t);
                const float p0 = __expf(sacc[mt][nt][0]) * (float)mc0.x;
                const float p1 = __expf(sacc[mt][nt][1]) * (float)mc0.y;
                const float p2 = __expf(sacc[mt][nt][2]) * (float)mc1.x;
                const float p3 = __expf(sacc[mt][nt][3]) * (float)mc1.y;
                rs[mt][0] += p0 + p1;
                rs[mt][1] += p2 + p3;
                __nv_bfloat16 h0 = bfh(p0), h1 = bfh(p1), h2 = bfh(p2), h3 = bfh(p3);
                const int j = nt >> 1, o = (nt & 1) * 2;
                pah[mt][j][o + 0] = pkb(h0, h1);
                pah[mt][j][o + 1] = pkb(h2, h3);
                pal[mt][j][o + 0] = pkb(bfl(p0, h0), bfl(p1, h1));
                pal[mt][j][o + 1] = pkb(bfl(p2, h2), bfl(p3, h3));
            }
        }

        // ctx += P V : V frags loaded once, reused by both q-halves.
#pragma unroll
        for (int ntp = 0; ntp < 4; ++ntp) {
#pragma unroll
            for (int j = 0; j < 2; ++j) {
                const uint32_t voff = stb + 2 * AKL +
                    (uint32_t)((j * 16 + (lane & 15)) * 72 + ntp * 16 +
                               8 * ((lane >> 4) & 1)) * 2;
                uint32_t vb_h[4], vb_l[4];
                ldsm4t(vb_h, voff);
                ldsm4t(vb_l, voff + AKL);
#pragma unroll
                for (int mt = 0; mt < 2; ++mt) {
                    float* c0 = ctx[mt][2 * ntp];
                    float* c1 = ctx[mt][2 * ntp + 1];
                    mma16816(c0, pah[mt][j], vb_h[0], vb_h[1]);
                    mma16816(c1, pah[mt][j], vb_h[2], vb_h[3]);
                    mma16816(c0, pah[mt][j], vb_l[0], vb_l[1]);
                    mma16816(c1, pah[mt][j], vb_l[2], vb_l[3]);
                    mma16816(c0, pal[mt][j], vb_h[0], vb_h[1]);
                    mma16816(c1, pal[mt][j], vb_h[2], vb_h[3]);
                }
            }
        }
    }

    // Rowsum reduction + normalized output.
#pragma unroll
    for (int mt = 0; mt < 2; ++mt) {
        float r0 = rs[mt][0], r1 = rs[mt][1];
        r0 += __shfl_xor_sync(0xffffffffu, r0, 1);
        r0 += __shfl_xor_sync(0xffffffffu, r0, 2);
        r1 += __shfl_xor_sync(0xffffffffu, r1, 1);
        r1 += __shfl_xor_sync(0xffffffffu, r1, 2);
        const float inv0 = 1.0f / (r0 + 1e-8f);
        const float inv1 = 1.0f / (r1 + 1e-8f);
        const int q0 = base_q + mt * 16 + g;
#pragma unroll
        for (int nt = 0; nt < 8; ++nt) {
            const int d = nt * 8 + lam * 2;
            float* o0 = out + ((size_t)b * NS + q0) * ND + h * NHD + d;
            *(float2*)o0 = make_float2(ctx[mt][nt][0] * inv0, ctx[mt][nt][1] * inv0);
            *(float2*)(o0 + (size_t)8 * ND) =
                make_float2(ctx[mt][nt][2] * inv1, ctx[mt][nt][3] * inv1);
        }
    }
}

// ---------------------------------------------------------------------------
extern "C" void kernel_launch(void* const* d_in, const int* in_sizes, int n_in,
                              void* d_out, int out_size) {
    (void)in_sizes; (void)n_in; (void)out_size;
    const float* x    = (const float*)d_in[0];
    const float* mask = (const float*)d_in[1];
    const float* Wq   = (const float*)d_in[2];
    const float* Wk   = (const float*)d_in[3];
    const float* Wv   = (const float*)d_in[4];
    float* out = (float*)d_out;

    cudaFuncSetAttribute(qkv_gemm_hmma,
                         cudaFuncAttributeMaxDynamicSharedMemorySize, NSTG * GST);
    cudaFuncSetAttribute(attn_tc,
                         cudaFuncAttributeMaxDynamicSharedMemorySize, 3 * AST);

    prep_mask<<<(NB * NS * NS) / 1024, 256>>>(mask);
    prep_x<<<(NB * NS * ND) / 1024, 256>>>(x);
    prep_w<<<dim3((ND * ND) / 1024, 3), 256>>>(Wq, Wk, Wv);
    qkv_gemm_hmma<<<dim3(ND / 128, (NB * NS) / 128, 3), 512, NSTG * GST>>>();
    attn_tc<<<dim3(NS / 128, NH, NB), 128, 3 * AST>>>(out);
}